// round 3
// baseline (speedup 1.0000x reference)
#include <cuda_runtime.h>
#include <math.h>
#include <stdint.h>

#define N_NODES  100000
#define N_EDGES  1600000
#define N_GRAPHS 2048
#define H        256
#define K1       128
#define NCLS     64

// ---------------- scratch (device globals; no allocation allowed) ----------
__device__ float g_deg[N_NODES];
__device__ float g_dinv[N_NODES];
__device__ int   g_src[N_EDGES];
__device__ int   g_dst[N_EDGES];
__device__ float g_norm[N_EDGES];
__device__ float g_h   [(size_t)N_NODES * H];
__device__ float g_obuf[(size_t)N_NODES * H];
__device__ float g_act [(size_t)N_NODES * H];
__device__ float g_sums[N_GRAPHS * H];
__device__ float g_cnt [N_GRAPHS];

// ---------------- init: deg=1 (self loop), sums=0, cnt=0 -------------------
__global__ void init_kernel() {
    int i = blockIdx.x * blockDim.x + threadIdx.x;
    if (i < N_NODES) g_deg[i] = 1.0f;
    if (i < N_GRAPHS * H) g_sums[i] = 0.0f;
    if (i < N_GRAPHS) g_cnt[i] = 0.0f;
}

// ---------------- edge pass 1: copy + degree count (int32 inputs!) ---------
__global__ void edge_deg_kernel(const int* __restrict__ ei) {
    int e = blockIdx.x * blockDim.x + threadIdx.x;
    if (e >= N_EDGES) return;
    int s = ei[e];
    int d = ei[N_EDGES + e];
    g_src[e] = s;
    g_dst[e] = d;
    atomicAdd(&g_deg[d], 1.0f);
}

__global__ void dinv_kernel() {
    int i = blockIdx.x * blockDim.x + threadIdx.x;
    if (i < N_NODES) g_dinv[i] = rsqrtf(fmaxf(g_deg[i], 1.0f));
}

__global__ void norm_kernel() {
    int e = blockIdx.x * blockDim.x + threadIdx.x;
    if (e < N_EDGES) g_norm[e] = g_dinv[g_src[e]] * g_dinv[g_dst[e]];
}

// ---------------- SGEMM: C[M,256] = A[M,K] @ W[K,256] ----------------------
// 64x64 tile, BK=16, 256 threads, 4x4 microtile.
__global__ __launch_bounds__(256) void gemm_kernel(
    const float* __restrict__ A, const float* __restrict__ W,
    float* __restrict__ C, int M, int K)
{
    __shared__ float As[16][68];   // [k][m], padded
    __shared__ float Bs[16][64];   // [k][n]

    const int bm = blockIdx.x * 64;
    const int bn = blockIdx.y * 64;
    const int tid = threadIdx.x;
    const int tx = tid & 15;       // n-tile coord
    const int ty = tid >> 4;       // m-tile coord

    float acc[4][4] = {};

    for (int kk = 0; kk < K; kk += 16) {
        #pragma unroll
        for (int i = 0; i < 4; i++) {
            int idx = tid + i * 256;          // 0..1023 over 64x16 A tile
            int r = idx >> 4, c = idx & 15;
            int gr = bm + r;
            As[c][r] = (gr < M) ? A[(size_t)gr * K + kk + c] : 0.0f;
        }
        #pragma unroll
        for (int i = 0; i < 4; i++) {
            int idx = tid + i * 256;          // 16x64 B tile
            int r = idx >> 6, c = idx & 63;
            Bs[r][c] = W[(size_t)(kk + r) * H + bn + c];
        }
        __syncthreads();

        #pragma unroll
        for (int k = 0; k < 16; k++) {
            float4 a = *(const float4*)&As[k][ty * 4];
            float4 b = *(const float4*)&Bs[k][tx * 4];
            float av[4] = {a.x, a.y, a.z, a.w};
            float bv[4] = {b.x, b.y, b.z, b.w};
            #pragma unroll
            for (int i = 0; i < 4; i++)
                #pragma unroll
                for (int j = 0; j < 4; j++)
                    acc[i][j] += av[i] * bv[j];
        }
        __syncthreads();
    }

    #pragma unroll
    for (int i = 0; i < 4; i++) {
        int row = bm + ty * 4 + i;
        if (row < M) {
            float4 v = make_float4(acc[i][0], acc[i][1], acc[i][2], acc[i][3]);
            *(float4*)&C[(size_t)row * H + bn + tx * 4] = v;
        }
    }
}

// ---------------- self-loop init: obuf[i] = h[i] * dinv[i]^2 ---------------
__global__ void selfloop_kernel() {
    int t = blockIdx.x * blockDim.x + threadIdx.x;   // N_NODES * 64 float4-chunks
    if (t >= N_NODES * (H / 4)) return;
    int node = t >> 6;
    float di = g_dinv[node];
    float s = di * di;
    float4 v = ((const float4*)g_h)[t];
    v.x *= s; v.y *= s; v.z *= s; v.w *= s;
    ((float4*)g_obuf)[t] = v;
}

// ---------------- edge scatter: obuf[d] += h[s] * norm ---------------------
__global__ __launch_bounds__(256) void scatter_kernel() {
    long long t = (long long)blockIdx.x * blockDim.x + threadIdx.x;
    if (t >= (long long)N_EDGES * (H / 4)) return;
    int e = (int)(t >> 6);
    int c = (int)(t & 63);
    int s = g_src[e];
    int d = g_dst[e];
    float nrm = g_norm[e];
    float4 v = ((const float4*)g_h)[(size_t)s * (H / 4) + c];
    float* p = &g_obuf[(size_t)d * H + c * 4];
    asm volatile("red.global.add.v4.f32 [%0], {%1,%2,%3,%4};"
                 :: "l"(p), "f"(v.x * nrm), "f"(v.y * nrm), "f"(v.z * nrm), "f"(v.w * nrm)
                 : "memory");
}

// ---------------- epilogue: act = relu(obuf + b) ---------------------------
__global__ void epi_kernel(const float* __restrict__ b) {
    int t = blockIdx.x * blockDim.x + threadIdx.x;
    if (t >= N_NODES * (H / 4)) return;
    int c = t & 63;
    float4 bv = ((const float4*)b)[c];
    float4 v = ((const float4*)g_obuf)[t];
    v.x = fmaxf(v.x + bv.x, 0.0f);
    v.y = fmaxf(v.y + bv.y, 0.0f);
    v.z = fmaxf(v.z + bv.z, 0.0f);
    v.w = fmaxf(v.w + bv.w, 0.0f);
    ((float4*)g_act)[t] = v;
}

// ---------------- pooling --------------------------------------------------
__global__ void pool_cnt_kernel(const int* __restrict__ batch) {
    int i = blockIdx.x * blockDim.x + threadIdx.x;
    if (i < N_NODES) atomicAdd(&g_cnt[batch[i]], 1.0f);
}

__global__ void pool_sum_kernel(const int* __restrict__ batch) {
    int t = blockIdx.x * blockDim.x + threadIdx.x;
    if (t >= N_NODES * (H / 4)) return;
    int node = t >> 6;
    int c = t & 63;
    int g = batch[node];
    float4 v = ((const float4*)g_act)[t];
    float* p = &g_sums[(size_t)g * H + c * 4];
    asm volatile("red.global.add.v4.f32 [%0], {%1,%2,%3,%4};"
                 :: "l"(p), "f"(v.x), "f"(v.y), "f"(v.z), "f"(v.w)
                 : "memory");
}

// ---------------- classifier + log_softmax ---------------------------------
__global__ __launch_bounds__(64) void classifier_kernel(
    const float* __restrict__ Wc, const float* __restrict__ bc,
    float* __restrict__ out)
{
    int g = blockIdx.x;
    int t = threadIdx.x;              // 64 threads, one per class
    __shared__ float gv[H];
    __shared__ float lg[NCLS];

    float inv = 1.0f / fmaxf(g_cnt[g], 1.0f);
    for (int k = t; k < H; k += NCLS) gv[k] = g_sums[g * H + k] * inv;
    __syncthreads();

    float acc = bc[t];
    #pragma unroll 8
    for (int k = 0; k < H; k++) acc += gv[k] * Wc[k * NCLS + t];
    lg[t] = acc;
    __syncthreads();

    float m = -INFINITY;
    #pragma unroll
    for (int i = 0; i < NCLS; i++) m = fmaxf(m, lg[i]);
    float s = 0.0f;
    #pragma unroll
    for (int i = 0; i < NCLS; i++) s += expf(lg[i] - m);
    out[g * NCLS + t] = acc - m - logf(s);
}

// ---------------- launch ---------------------------------------------------
extern "C" void kernel_launch(void* const* d_in, const int* in_sizes, int n_in,
                              void* d_out, int out_size)
{
    const float* x     = (const float*)d_in[0];
    const int*   ei    = (const int*)d_in[1];
    const int*   batch = (const int*)d_in[2];
    const float* W1    = (const float*)d_in[3];
    const float* b1    = (const float*)d_in[4];
    const float* W2    = (const float*)d_in[5];
    const float* b2    = (const float*)d_in[6];
    const float* Wc    = (const float*)d_in[7];
    const float* bc    = (const float*)d_in[8];
    float* out = (float*)d_out;

    float *p_h, *p_act;
    cudaGetSymbolAddress((void**)&p_h,   g_h);
    cudaGetSymbolAddress((void**)&p_act, g_act);

    const int TB = 256;
    const int nf4 = N_NODES * (H / 4);           // 6.4M node-feature float4 chunks
    const long long ef4 = (long long)N_EDGES * (H / 4);

    // init + degree + norms
    {
        int n = N_GRAPHS * H;
        if (N_NODES > n) n = N_NODES;
        init_kernel<<<(n + TB - 1) / TB, TB>>>();
    }
    edge_deg_kernel<<<(N_EDGES + TB - 1) / TB, TB>>>(ei);
    dinv_kernel<<<(N_NODES + TB - 1) / TB, TB>>>();
    norm_kernel<<<(N_EDGES + TB - 1) / TB, TB>>>();

    dim3 gemm_grid((N_NODES + 63) / 64, H / 64);

    // ----- layer 1 -----
    gemm_kernel<<<gemm_grid, 256>>>(x, W1, p_h, N_NODES, K1);
    selfloop_kernel<<<(nf4 + TB - 1) / TB, TB>>>();
    scatter_kernel<<<(unsigned)((ef4 + TB - 1) / TB), TB>>>();
    epi_kernel<<<(nf4 + TB - 1) / TB, TB>>>(b1);

    // ----- layer 2 -----
    gemm_kernel<<<gemm_grid, 256>>>(p_act, W2, p_h, N_NODES, H);
    selfloop_kernel<<<(nf4 + TB - 1) / TB, TB>>>();
    scatter_kernel<<<(unsigned)((ef4 + TB - 1) / TB), TB>>>();
    epi_kernel<<<(nf4 + TB - 1) / TB, TB>>>(b2);

    // ----- pool + classify -----
    pool_cnt_kernel<<<(N_NODES + TB - 1) / TB, TB>>>(batch);
    pool_sum_kernel<<<(nf4 + TB - 1) / TB, TB>>>(batch);
    classifier_kernel<<<N_GRAPHS, NCLS>>>(Wc, bc, out);
}

// round 4
// speedup vs baseline: 3.2978x; 3.2978x over previous
#include <cuda_runtime.h>
#include <cuda_bf16.h>
#include <math.h>
#include <stdint.h>

#define N_NODES  100000
#define N_EDGES  1600000
#define N_GRAPHS 2048
#define H        256
#define K1       128
#define NCLS     64
#define NB_SCAN  ((N_NODES + 255) / 256)   // 391

// ---------------- scratch (device globals) ---------------------------------
__device__ int   g_degi[N_NODES];
__device__ int   g_rowptr[N_NODES + 1];
__device__ int   g_cur[N_NODES];
__device__ int   g_bsum[512];
__device__ int   g_boff[512];
__device__ float g_dinv[N_NODES];
__device__ int   g_csrc[N_EDGES];
__device__ float g_cnorm[N_EDGES];
__device__ float g_aggx[(size_t)N_NODES * K1];
__device__ float g_act1[(size_t)N_NODES * H];
__device__ float g_agg2[(size_t)N_NODES * H];
__device__ __nv_bfloat16 g_w1h[H * K1];
__device__ __nv_bfloat16 g_w1l[H * K1];
__device__ __nv_bfloat16 g_w2h[H * H];
__device__ __nv_bfloat16 g_w2l[H * H];
__device__ float g_sums[N_GRAPHS * H];
__device__ float g_cnt [N_GRAPHS];

__device__ __forceinline__ uint32_t s2u(const void* p) {
    return (uint32_t)__cvta_generic_to_shared(p);
}

// ---------------- init ------------------------------------------------------
__global__ void init_kernel() {
    int i = blockIdx.x * blockDim.x + threadIdx.x;
    if (i < N_NODES) g_degi[i] = 0;
    if (i < N_GRAPHS * H) g_sums[i] = 0.0f;
    if (i < N_GRAPHS) g_cnt[i] = 0.0f;
}

// ---------------- degree histogram ------------------------------------------
__global__ void deg_kernel(const int* __restrict__ ei) {
    int e = blockIdx.x * blockDim.x + threadIdx.x;
    if (e < N_EDGES) atomicAdd(&g_degi[ei[N_EDGES + e]], 1);
}

__global__ void dinv_kernel() {
    int i = blockIdx.x * blockDim.x + threadIdx.x;
    if (i < N_NODES) g_dinv[i] = rsqrtf((float)(g_degi[i] + 1));
}

// ---------------- 3-phase exclusive scan over degrees -----------------------
__global__ void scan1_kernel() {
    __shared__ int sh[256];
    int i = blockIdx.x * 256 + threadIdx.x;
    int v = (i < N_NODES) ? g_degi[i] : 0;
    sh[threadIdx.x] = v;
    __syncthreads();
    for (int off = 1; off < 256; off <<= 1) {
        int t = (threadIdx.x >= off) ? sh[threadIdx.x - off] : 0;
        __syncthreads();
        sh[threadIdx.x] += t;
        __syncthreads();
    }
    if (i < N_NODES) g_rowptr[i] = sh[threadIdx.x] - v;   // exclusive, block-local
    if (threadIdx.x == 255) g_bsum[blockIdx.x] = sh[255];
}

__global__ void scan2_kernel() {
    __shared__ int sh[512];
    int t = threadIdx.x;
    int v = (t < NB_SCAN) ? g_bsum[t] : 0;
    sh[t] = v;
    __syncthreads();
    for (int off = 1; off < 512; off <<= 1) {
        int u = (t >= off) ? sh[t - off] : 0;
        __syncthreads();
        sh[t] += u;
        __syncthreads();
    }
    if (t < NB_SCAN) g_boff[t] = sh[t] - v;               // exclusive block offsets
}

__global__ void scan3_kernel() {
    int i = blockIdx.x * 256 + threadIdx.x;
    if (i < N_NODES) {
        int r = g_rowptr[i] + g_boff[blockIdx.x];
        g_rowptr[i] = r;
        g_cur[i] = r;
    }
    if (i == 0) g_rowptr[N_NODES] = N_EDGES;
}

// ---------------- CSR fill ---------------------------------------------------
__global__ void fill_kernel(const int* __restrict__ ei) {
    int e = blockIdx.x * blockDim.x + threadIdx.x;
    if (e >= N_EDGES) return;
    int s = ei[e];
    int d = ei[N_EDGES + e];
    int pos = atomicAdd(&g_cur[d], 1);
    g_csrc[pos]  = s;
    g_cnorm[pos] = g_dinv[s] * g_dinv[d];
}

// ---------------- weight transpose + bf16 hi/lo split ------------------------
__global__ void wsplit_kernel(const float* __restrict__ W,
                              __nv_bfloat16* __restrict__ Wh,
                              __nv_bfloat16* __restrict__ Wl, int K) {
    int idx = blockIdx.x * blockDim.x + threadIdx.x;
    if (idx >= K * H) return;
    int k = idx / H, n = idx % H;
    float w = W[idx];
    __nv_bfloat16 hi = __float2bfloat16_rn(w);
    float lo = w - __bfloat162float(hi);
    Wh[n * K + k] = hi;
    Wl[n * K + k] = __float2bfloat16_rn(lo);
}

// ---------------- aggregation 1: aggx = S_hat @ x   (width 128) --------------
__global__ __launch_bounds__(256) void agg1_kernel(const float* __restrict__ x) {
    int node = blockIdx.x * 8 + (threadIdx.x >> 5);
    if (node >= N_NODES) return;
    int lane = threadIdx.x & 31;
    const float4* X = (const float4*)x;

    float di = g_dinv[node];
    float sl = di * di;
    float4 a = X[(size_t)node * 32 + lane];
    float4 acc = make_float4(a.x * sl, a.y * sl, a.z * sl, a.w * sl);

    int i = g_rowptr[node], end = g_rowptr[node + 1];
    for (; i + 4 <= end; i += 4) {
        int s0 = g_csrc[i], s1 = g_csrc[i+1], s2 = g_csrc[i+2], s3 = g_csrc[i+3];
        float w0 = g_cnorm[i], w1 = g_cnorm[i+1], w2 = g_cnorm[i+2], w3 = g_cnorm[i+3];
        float4 v0 = X[(size_t)s0 * 32 + lane];
        float4 v1 = X[(size_t)s1 * 32 + lane];
        float4 v2 = X[(size_t)s2 * 32 + lane];
        float4 v3 = X[(size_t)s3 * 32 + lane];
        acc.x += v0.x*w0 + v1.x*w1 + v2.x*w2 + v3.x*w3;
        acc.y += v0.y*w0 + v1.y*w1 + v2.y*w2 + v3.y*w3;
        acc.z += v0.z*w0 + v1.z*w1 + v2.z*w2 + v3.z*w3;
        acc.w += v0.w*w0 + v1.w*w1 + v2.w*w2 + v3.w*w3;
    }
    for (; i < end; i++) {
        int s = g_csrc[i]; float w = g_cnorm[i];
        float4 v = X[(size_t)s * 32 + lane];
        acc.x += v.x*w; acc.y += v.y*w; acc.z += v.z*w; acc.w += v.w*w;
    }
    ((float4*)g_aggx)[(size_t)node * 32 + lane] = acc;
}

// ---------------- aggregation 2: agg2 = S_hat @ act1 (width 256) -------------
__global__ __launch_bounds__(256) void agg2_kernel(const float* __restrict__ h) {
    int node = blockIdx.x * 8 + (threadIdx.x >> 5);
    if (node >= N_NODES) return;
    int lane = threadIdx.x & 31;
    const float4* X = (const float4*)h;

    float di = g_dinv[node];
    float sl = di * di;
    float4 a0 = X[(size_t)node * 64 + lane];
    float4 a1 = X[(size_t)node * 64 + 32 + lane];
    float4 acc0 = make_float4(a0.x*sl, a0.y*sl, a0.z*sl, a0.w*sl);
    float4 acc1 = make_float4(a1.x*sl, a1.y*sl, a1.z*sl, a1.w*sl);

    int i = g_rowptr[node], end = g_rowptr[node + 1];
    for (; i + 2 <= end; i += 2) {
        int s0 = g_csrc[i], s1 = g_csrc[i+1];
        float w0 = g_cnorm[i], w1 = g_cnorm[i+1];
        float4 v00 = X[(size_t)s0 * 64 + lane];
        float4 v01 = X[(size_t)s0 * 64 + 32 + lane];
        float4 v10 = X[(size_t)s1 * 64 + lane];
        float4 v11 = X[(size_t)s1 * 64 + 32 + lane];
        acc0.x += v00.x*w0 + v10.x*w1;  acc0.y += v00.y*w0 + v10.y*w1;
        acc0.z += v00.z*w0 + v10.z*w1;  acc0.w += v00.w*w0 + v10.w*w1;
        acc1.x += v01.x*w0 + v11.x*w1;  acc1.y += v01.y*w0 + v11.y*w1;
        acc1.z += v01.z*w0 + v11.z*w1;  acc1.w += v01.w*w0 + v11.w*w1;
    }
    for (; i < end; i++) {
        int s = g_csrc[i]; float w = g_cnorm[i];
        float4 v0 = X[(size_t)s * 64 + lane];
        float4 v1 = X[(size_t)s * 64 + 32 + lane];
        acc0.x += v0.x*w; acc0.y += v0.y*w; acc0.z += v0.z*w; acc0.w += v0.w*w;
        acc1.x += v1.x*w; acc1.y += v1.y*w; acc1.z += v1.z*w; acc1.w += v1.w*w;
    }
    ((float4*)g_agg2)[(size_t)node * 64 + lane] = acc0;
    ((float4*)g_agg2)[(size_t)node * 64 + 32 + lane] = acc1;
}

// ---------------- bf16-split tensor-core GEMM --------------------------------
// C[M,256] = A[M,K] @ W[K,256], computed as AhWh + AhWl + AlWh (fp32 accum).
// BM=128, BN=64, BK=32, 256 threads (8 warps, 4(m) x 2(n), 32x32 per warp).
// POOL=false: out[row*256+col] = relu(c + bias)
// POOL=true : red.add.v2 into g_sums[batch[row]*256+col] of relu(c + bias)
template <bool POOL>
__global__ __launch_bounds__(256, 1) void gemm_kernel(
    const float* __restrict__ A,
    const __nv_bfloat16* __restrict__ Wth,   // [256][K]
    const __nv_bfloat16* __restrict__ Wtl,   // [256][K]
    const float* __restrict__ bias,
    float* __restrict__ out,
    const int* __restrict__ batch,
    int M, int K)
{
    __shared__ __align__(16) __nv_bfloat16 Ah[128][40];
    __shared__ __align__(16) __nv_bfloat16 Al[128][40];
    __shared__ __align__(16) __nv_bfloat16 Bh[64][40];
    __shared__ __align__(16) __nv_bfloat16 Bl[64][40];

    const int tid  = threadIdx.x;
    const int lane = tid & 31;
    const int wid  = tid >> 5;
    const int wm   = wid & 3;          // warp m index (0..3)
    const int wn   = wid >> 2;         // warp n index (0..1)
    const int bm   = blockIdx.x * 128;
    const int bn   = blockIdx.y * 64;

    float acc[2][4][4];
    #pragma unroll
    for (int i = 0; i < 2; i++)
        #pragma unroll
        for (int j = 0; j < 4; j++)
            #pragma unroll
            for (int l = 0; l < 4; l++) acc[i][j][l] = 0.0f;

    const int ar = tid >> 3;           // 0..31
    const int aq = (tid & 7) * 4;      // float col within BK
    const int wr = tid >> 2;           // 0..63
    const int wq = (tid & 3) * 8;      // bf16 col within BK

    const int grp = lane >> 3, lr = lane & 7;

    for (int kk = 0; kk < K; kk += 32) {
        // ---- load A tile (fp32 -> bf16 hi/lo split) ----
        #pragma unroll
        for (int st = 0; st < 4; st++) {
            int row = bm + st * 32 + ar;
            float4 a = make_float4(0.f, 0.f, 0.f, 0.f);
            if (row < M) a = *(const float4*)&A[(size_t)row * K + kk + aq];
            __nv_bfloat16 hx = __float2bfloat16_rn(a.x);
            __nv_bfloat16 hy = __float2bfloat16_rn(a.y);
            __nv_bfloat16 hz = __float2bfloat16_rn(a.z);
            __nv_bfloat16 hw = __float2bfloat16_rn(a.w);
            __nv_bfloat16 lx = __float2bfloat16_rn(a.x - __bfloat162float(hx));
            __nv_bfloat16 ly = __float2bfloat16_rn(a.y - __bfloat162float(hy));
            __nv_bfloat16 lz = __float2bfloat16_rn(a.z - __bfloat162float(hz));
            __nv_bfloat16 lw = __float2bfloat16_rn(a.w - __bfloat162float(hw));
            int r = st * 32 + ar;
            *(__nv_bfloat162*)&Ah[r][aq]     = __halves2bfloat162(hx, hy);
            *(__nv_bfloat162*)&Ah[r][aq + 2] = __halves2bfloat162(hz, hw);
            *(__nv_bfloat162*)&Al[r][aq]     = __halves2bfloat162(lx, ly);
            *(__nv_bfloat162*)&Al[r][aq + 2] = __halves2bfloat162(lz, lw);
        }
        // ---- load W tiles (already bf16, [n][k] layout) ----
        {
            const uint4 wh = *(const uint4*)&Wth[(size_t)(bn + wr) * K + kk + wq];
            const uint4 wl = *(const uint4*)&Wtl[(size_t)(bn + wr) * K + kk + wq];
            uint2* dh = (uint2*)&Bh[wr][wq];
            dh[0] = make_uint2(wh.x, wh.y);
            dh[1] = make_uint2(wh.z, wh.w);
            uint2* dl = (uint2*)&Bl[wr][wq];
            dl[0] = make_uint2(wl.x, wl.y);
            dl[1] = make_uint2(wl.z, wl.w);
        }
        __syncthreads();

        #pragma unroll
        for (int ks = 0; ks < 2; ks++) {
            const int k0 = ks * 16;
            uint32_t fah[2][4], fal[2][4], fbh[8], fbl[8];
            // A fragments (2 m-tiles, hi+lo)
            #pragma unroll
            for (int mt = 0; mt < 2; mt++) {
                int arow = wm * 32 + mt * 16 + lr + ((grp & 1) ? 8 : 0);
                int acol = k0 + ((grp & 2) ? 8 : 0);
                uint32_t ad = s2u(&Ah[arow][acol]);
                asm volatile("ldmatrix.sync.aligned.m8n8.x4.shared.b16 {%0,%1,%2,%3}, [%4];"
                             : "=r"(fah[mt][0]), "=r"(fah[mt][1]), "=r"(fah[mt][2]), "=r"(fah[mt][3])
                             : "r"(ad));
                uint32_t ad2 = s2u(&Al[arow][acol]);
                asm volatile("ldmatrix.sync.aligned.m8n8.x4.shared.b16 {%0,%1,%2,%3}, [%4];"
                             : "=r"(fal[mt][0]), "=r"(fal[mt][1]), "=r"(fal[mt][2]), "=r"(fal[mt][3])
                             : "r"(ad2));
            }
            // B fragments (4 n-tiles via 2 x4 loads, hi+lo)
            #pragma unroll
            for (int bp = 0; bp < 2; bp++) {
                int brow = wn * 32 + bp * 16 + lr + ((grp & 2) ? 8 : 0);
                int bcol = k0 + ((grp & 1) ? 8 : 0);
                uint32_t bd = s2u(&Bh[brow][bcol]);
                asm volatile("ldmatrix.sync.aligned.m8n8.x4.shared.b16 {%0,%1,%2,%3}, [%4];"
                             : "=r"(fbh[bp*4+0]), "=r"(fbh[bp*4+1]), "=r"(fbh[bp*4+2]), "=r"(fbh[bp*4+3])
                             : "r"(bd));
                uint32_t bd2 = s2u(&Bl[brow][bcol]);
                asm volatile("ldmatrix.sync.aligned.m8n8.x4.shared.b16 {%0,%1,%2,%3}, [%4];"
                             : "=r"(fbl[bp*4+0]), "=r"(fbl[bp*4+1]), "=r"(fbl[bp*4+2]), "=r"(fbl[bp*4+3])
                             : "r"(bd2));
            }
            // MMAs: AhWh + AhWl + AlWh
            #pragma unroll
            for (int mt = 0; mt < 2; mt++) {
                #pragma unroll
                for (int nt = 0; nt < 4; nt++) {
                    float* c = acc[mt][nt];
                    uint32_t b0 = fbh[nt*2], b1 = fbh[nt*2+1];
                    uint32_t l0 = fbl[nt*2], l1 = fbl[nt*2+1];
                    asm volatile("mma.sync.aligned.m16n8k16.row.col.f32.bf16.bf16.f32 "
                                 "{%0,%1,%2,%3}, {%4,%5,%6,%7}, {%8,%9}, {%0,%1,%2,%3};"
                                 : "+f"(c[0]), "+f"(c[1]), "+f"(c[2]), "+f"(c[3])
                                 : "r"(fah[mt][0]), "r"(fah[mt][1]), "r"(fah[mt][2]), "r"(fah[mt][3]),
                                   "r"(b0), "r"(b1));
                    asm volatile("mma.sync.aligned.m16n8k16.row.col.f32.bf16.bf16.f32 "
                                 "{%0,%1,%2,%3}, {%4,%5,%6,%7}, {%8,%9}, {%0,%1,%2,%3};"
                                 : "+f"(c[0]), "+f"(c[1]), "+f"(c[2]), "+f"(c[3])
                                 : "r"(fah[mt][0]), "r"(fah[mt][1]), "r"(fah[mt][2]), "r"(fah[mt][3]),
                                   "r"(l0), "r"(l1));
                    asm volatile("mma.sync.aligned.m16n8k16.row.col.f32.bf16.bf16.f32 "
                                 "{%0,%1,%2,%3}, {%4,%5,%6,%7}, {%8,%9}, {%0,%1,%2,%3};"
                                 : "+f"(c[0]), "+f"(c[1]), "+f"(c[2]), "+f"(c[3])
                                 : "r"(fal[mt][0]), "r"(fal[mt][1]), "r"(fal[mt][2]), "r"(fal[mt][3]),
                                   "r"(b0), "r"(b1));
                }
            }
        }
        __syncthreads();
    }

    // ---- epilogue ----
    const int qr = lane >> 2;
    const int qc = (lane & 3) * 2;
    #pragma unroll
    for (int mt = 0; mt < 2; mt++) {
        #pragma unroll
        for (int nt = 0; nt < 4; nt++) {
            int col = bn + wn * 32 + nt * 8 + qc;
            float bx = bias[col], by = bias[col + 1];
            int row0 = bm + wm * 32 + mt * 16 + qr;
            int row1 = row0 + 8;
            float v00 = fmaxf(acc[mt][nt][0] + bx, 0.f);
            float v01 = fmaxf(acc[mt][nt][1] + by, 0.f);
            float v10 = fmaxf(acc[mt][nt][2] + bx, 0.f);
            float v11 = fmaxf(acc[mt][nt][3] + by, 0.f);
            if (POOL) {
                if (row0 < M) {
                    float* p = &g_sums[(size_t)batch[row0] * H + col];
                    asm volatile("red.global.add.v2.f32 [%0], {%1,%2};"
                                 :: "l"(p), "f"(v00), "f"(v01) : "memory");
                }
                if (row1 < M) {
                    float* p = &g_sums[(size_t)batch[row1] * H + col];
                    asm volatile("red.global.add.v2.f32 [%0], {%1,%2};"
                                 :: "l"(p), "f"(v10), "f"(v11) : "memory");
                }
            } else {
                if (row0 < M) *(float2*)&out[(size_t)row0 * H + col] = make_float2(v00, v01);
                if (row1 < M) *(float2*)&out[(size_t)row1 * H + col] = make_float2(v10, v11);
            }
        }
    }
}

// ---------------- pooling count ----------------------------------------------
__global__ void pool_cnt_kernel(const int* __restrict__ batch) {
    int i = blockIdx.x * blockDim.x + threadIdx.x;
    if (i < N_NODES) atomicAdd(&g_cnt[batch[i]], 1.0f);
}

// ---------------- classifier + log_softmax -----------------------------------
__global__ __launch_bounds__(64) void classifier_kernel(
    const float* __restrict__ Wc, const float* __restrict__ bc,
    float* __restrict__ out)
{
    int g = blockIdx.x;
    int t = threadIdx.x;
    __shared__ float gv[H];
    __shared__ float lg[NCLS];

    float inv = 1.0f / fmaxf(g_cnt[g], 1.0f);
    for (int k = t; k < H; k += NCLS) gv[k] = g_sums[g * H + k] * inv;
    __syncthreads();

    float acc = bc[t];
    #pragma unroll 8
    for (int k = 0; k < H; k++) acc += gv[k] * Wc[k * NCLS + t];
    lg[t] = acc;
    __syncthreads();

    float m = -INFINITY;
    #pragma unroll
    for (int i = 0; i < NCLS; i++) m = fmaxf(m, lg[i]);
    float s = 0.0f;
    #pragma unroll
    for (int i = 0; i < NCLS; i++) s += expf(lg[i] - m);
    out[g * NCLS + t] = acc - m - logf(s);
}

// ---------------- launch ------------------------------------------------------
extern "C" void kernel_launch(void* const* d_in, const int* in_sizes, int n_in,
                              void* d_out, int out_size)
{
    const float* x     = (const float*)d_in[0];
    const int*   ei    = (const int*)d_in[1];
    const int*   batch = (const int*)d_in[2];
    const float* W1    = (const float*)d_in[3];
    const float* b1    = (const float*)d_in[4];
    const float* W2    = (const float*)d_in[5];
    const float* b2    = (const float*)d_in[6];
    const float* Wc    = (const float*)d_in[7];
    const float* bc    = (const float*)d_in[8];
    float* out = (float*)d_out;

    float *p_aggx, *p_act1, *p_agg2;
    __nv_bfloat16 *p_w1h, *p_w1l, *p_w2h, *p_w2l;
    cudaGetSymbolAddress((void**)&p_aggx, g_aggx);
    cudaGetSymbolAddress((void**)&p_act1, g_act1);
    cudaGetSymbolAddress((void**)&p_agg2, g_agg2);
    cudaGetSymbolAddress((void**)&p_w1h, g_w1h);
    cudaGetSymbolAddress((void**)&p_w1l, g_w1l);
    cudaGetSymbolAddress((void**)&p_w2h, g_w2h);
    cudaGetSymbolAddress((void**)&p_w2l, g_w2l);

    const int TB = 256;

    // init
    {
        int n = N_GRAPHS * H;
        if (N_NODES > n) n = N_NODES;
        init_kernel<<<(n + TB - 1) / TB, TB>>>();
    }

    // CSR build
    deg_kernel<<<(N_EDGES + TB - 1) / TB, TB>>>(ei);
    dinv_kernel<<<(N_NODES + TB - 1) / TB, TB>>>();
    scan1_kernel<<<NB_SCAN, 256>>>();
    scan2_kernel<<<1, 512>>>();
    scan3_kernel<<<NB_SCAN, 256>>>();
    fill_kernel<<<(N_EDGES + TB - 1) / TB, TB>>>(ei);

    // weight splits
    wsplit_kernel<<<(K1 * H + TB - 1) / TB, TB>>>(W1, p_w1h, p_w1l, K1);
    wsplit_kernel<<<(H * H + TB - 1) / TB, TB>>>(W2, p_w2h, p_w2l, H);

    dim3 gemm_grid((N_NODES + 127) / 128, H / 64);

    // layer 1: aggregate-then-transform
    agg1_kernel<<<(N_NODES + 7) / 8, 256>>>(x);
    gemm_kernel<false><<<gemm_grid, 256>>>(p_aggx, p_w1h, p_w1l, b1, p_act1,
                                           batch, N_NODES, K1);

    // layer 2: aggregate-then-transform, pooled epilogue
    agg2_kernel<<<(N_NODES + 7) / 8, 256>>>(p_act1);
    gemm_kernel<true><<<gemm_grid, 256>>>(p_agg2, p_w2h, p_w2l, b2, nullptr,
                                          batch, N_NODES, H);

    // pool count + classifier
    pool_cnt_kernel<<<(N_NODES + TB - 1) / TB, TB>>>(batch);
    classifier_kernel<<<N_GRAPHS, NCLS>>>(Wc, bc, out);
}